// round 10
// baseline (speedup 1.0000x reference)
#include <cuda_runtime.h>
#include <cuda_fp16.h>
#include <cstdint>

#define BATCH 2
#define SEQ   2048
#define EMB   1024
#define NHEAD 16
#define HS    64
#define MROWS 4096
// exp(s/32) = 2^(s * CEXP), folded into Q at projection time
#define CEXP  0.045084294f

// ---------------- scratch (device globals) ----------------
__device__ __half g_xh[MROWS * EMB];
__device__ __half g_Wqh[EMB * EMB];   // fp16, K-major [k][n]
__device__ __half g_Wkh[EMB * EMB];
__device__ __half g_Wvh[EMB * EMB];
__device__ __half g_Wph[EMB * EMB];
__device__ __half g_Qh[MROWS * EMB];  // [b,h,t,d], pre-scaled by CEXP
__device__ __half g_Kh[MROWS * EMB];  // [b,h,t,d]
__device__ __half g_Vh[MROWS * EMB];  // [b,h,t,d]
__device__ __half g_Ah[MROWS * EMB];  // [b*t, h*64+d]

// ---------------- helpers ----------------
__device__ __forceinline__ uint32_t smem_u32(const void* p) {
    uint32_t a;
    asm("{ .reg .u64 t; cvta.to.shared.u64 t, %1; cvt.u32.u64 %0, t; }" : "=r"(a) : "l"(p));
    return a;
}
__device__ __forceinline__ void cp16(uint32_t saddr, const void* g) {
    asm volatile("cp.async.cg.shared.global [%0], [%1], 16;" :: "r"(saddr), "l"(g));
}
#define CP_COMMIT() asm volatile("cp.async.commit_group;" ::: "memory")
#define CP_WAIT0()  asm volatile("cp.async.wait_group 0;" ::: "memory")
#define CP_WAIT1()  asm volatile("cp.async.wait_group 1;" ::: "memory")

__device__ __forceinline__ void hmma(float* c, const uint32_t* a, uint32_t b0, uint32_t b1) {
    asm volatile("mma.sync.aligned.m16n8k16.row.col.f32.f16.f16.f32 "
        "{%0,%1,%2,%3}, {%4,%5,%6,%7}, {%8,%9}, {%0,%1,%2,%3};"
        : "+f"(c[0]), "+f"(c[1]), "+f"(c[2]), "+f"(c[3])
        : "r"(a[0]), "r"(a[1]), "r"(a[2]), "r"(a[3]), "r"(b0), "r"(b1));
}
__device__ __forceinline__ void ldsm4(uint32_t* r, uint32_t addr) {
    asm volatile("ldmatrix.sync.aligned.m8n8.x4.shared.b16 {%0,%1,%2,%3}, [%4];"
        : "=r"(r[0]), "=r"(r[1]), "=r"(r[2]), "=r"(r[3]) : "r"(addr));
}
__device__ __forceinline__ void ldsm4t(uint32_t* r, uint32_t addr) {
    asm volatile("ldmatrix.sync.aligned.m8n8.x4.trans.shared.b16 {%0,%1,%2,%3}, [%4];"
        : "=r"(r[0]), "=r"(r[1]), "=r"(r[2]), "=r"(r[3]) : "r"(addr));
}
__device__ __forceinline__ uint32_t pack2(float a, float b) {
    __half2 h = __floats2half2_rn(a, b);
    return *(uint32_t*)&h;
}
__device__ __forceinline__ uint32_t h2exp2(uint32_t x) {
    uint32_t r;
    asm("ex2.approx.f16x2 %0, %1;" : "=r"(r) : "r"(x));
    return r;
}
#define ONES2 0x3C003C00u   // half2(1, 1)

// ---------------- fused conversion: x + 4 weights, one kernel ----------------
// float4-index space: x [0,1M), Wq [1M,1.25M), Wk [1.25M,1.5M),
// Wv [1.5M,1.75M), Wp [1.75M,2M). Each thread handles 2 float4s.
#define XF4 (MROWS * EMB / 4)          // 1048576
#define WF4 (EMB * EMB / 4)            // 262144

__global__ __launch_bounds__(256)
void cvt_all_kernel(const float* __restrict__ x,
                    const float* __restrict__ Wq, const float* __restrict__ Wk,
                    const float* __restrict__ Wv, const float* __restrict__ Wp,
                    __half* __restrict__ xh,
                    __half* __restrict__ wq, __half* __restrict__ wk,
                    __half* __restrict__ wv, __half* __restrict__ wp)
{
    const int base = blockIdx.x * 256 + threadIdx.x;
    #pragma unroll
    for (int j = 0; j < 2; ++j) {
        int idx = base + j * XF4;      // covers [0, 2M)
        const float* src;
        __half* dst;
        int off;
        if (idx < XF4)                { src = x;  dst = xh; off = idx; }
        else if (idx < XF4 + WF4)     { src = Wq; dst = wq; off = idx - XF4; }
        else if (idx < XF4 + 2 * WF4) { src = Wk; dst = wk; off = idx - XF4 - WF4; }
        else if (idx < XF4 + 3 * WF4) { src = Wv; dst = wv; off = idx - XF4 - 2 * WF4; }
        else                          { src = Wp; dst = wp; off = idx - XF4 - 3 * WF4; }
        float4 v = *(const float4*)(src + (size_t)off * 4);
        *(__half2*)(dst + (size_t)off * 4)     = __floats2half2_rn(v.x, v.y);
        *(__half2*)(dst + (size_t)off * 4 + 2) = __floats2half2_rn(v.z, v.w);
    }
}

// ---------------- HMMA GEMM: C[M,N] = A[M,K] * B[K,N] (round-5 proven) -------
// 128x128 tile, BK=32, 256 threads (8 warps, 64x32 warp tiles), cp.async 2-stage.
#define ASTR 40    // A smem stride (32 + 8 pad halves)
#define BSTR 136   // B smem stride (128 + 8 pad halves)

template <int FUSED>
__global__ __launch_bounds__(256)
void gemm_hmma(const __half* __restrict__ A,
               const __half* __restrict__ B0, const __half* __restrict__ B1,
               const __half* __restrict__ B2,
               __half* __restrict__ D0, __half* __restrict__ D1,
               __half* __restrict__ D2,
               float* __restrict__ Dout, const float* __restrict__ bias)
{
    __shared__ __half As[2][128][ASTR];
    __shared__ __half Bs[2][32][BSTR];

    const int tid = threadIdx.x, wid = tid >> 5, lane = tid & 31;
    const int bn = blockIdx.x * 128, bm = blockIdx.y * 128;
    const int z = FUSED ? blockIdx.z : 0;
    const __half* B = FUSED ? ((z == 0) ? B0 : (z == 1) ? B1 : B2) : B0;
    const int mw = (wid & 1) * 64, nw = (wid >> 1) * 32;
    const int lr = lane >> 2, lc2 = 2 * (lane & 3);

    float acc[4][4][4];
    #pragma unroll
    for (int i = 0; i < 4; i++)
        #pragma unroll
        for (int j = 0; j < 4; j++)
            #pragma unroll
            for (int f = 0; f < 4; f++) acc[i][j][f] = 0.f;

    const int arow = tid >> 1, acb = (tid & 1) * 2;
    const int br0 = tid >> 4, bc0 = tid & 15;
    const int br1 = (tid + 256) >> 4, bc1 = bc0;

    {
        const __half* Ag = A + (size_t)(bm + arow) * EMB;
        #pragma unroll
        for (int i = 0; i < 2; i++)
            cp16(smem_u32(&As[0][arow][(acb + i) * 8]), Ag + (acb + i) * 8);
        cp16(smem_u32(&Bs[0][br0][bc0 * 8]), B + (size_t)br0 * EMB + bn + bc0 * 8);
        cp16(smem_u32(&Bs[0][br1][bc1 * 8]), B + (size_t)br1 * EMB + bn + bc1 * 8);
        CP_COMMIT();
    }

    const int a_r = lane & 15, a_c = 8 * (lane >> 4);
    const int b_r = (lane & 7) + 8 * ((lane >> 3) & 1), b_c = 8 * (lane >> 4);

    for (int kt = 0; kt < 32; ++kt) {
        if (kt + 1 < 32) {
            const int k0n = (kt + 1) * 32;
            const int nb = (kt + 1) & 1;
            const __half* Ag = A + (size_t)(bm + arow) * EMB + k0n;
            #pragma unroll
            for (int i = 0; i < 2; i++)
                cp16(smem_u32(&As[nb][arow][(acb + i) * 8]), Ag + (acb + i) * 8);
            cp16(smem_u32(&Bs[nb][br0][bc0 * 8]), B + (size_t)(k0n + br0) * EMB + bn + bc0 * 8);
            cp16(smem_u32(&Bs[nb][br1][bc1 * 8]), B + (size_t)(k0n + br1) * EMB + bn + bc1 * 8);
            CP_COMMIT();
            CP_WAIT1();
        } else {
            CP_WAIT0();
        }
        __syncthreads();
        const int cb = kt & 1;
        #pragma unroll
        for (int kk = 0; kk < 2; ++kk) {
            uint32_t a[4][4], b[4][2];
            #pragma unroll
            for (int am = 0; am < 4; ++am)
                ldsm4(a[am], smem_u32(&As[cb][mw + 16 * am + a_r][16 * kk + a_c]));
            #pragma unroll
            for (int anp = 0; anp < 2; ++anp) {
                uint32_t bt[4];
                ldsm4t(bt, smem_u32(&Bs[cb][16 * kk + b_r][nw + 16 * anp + b_c]));
                b[2 * anp][0] = bt[0]; b[2 * anp][1] = bt[1];
                b[2 * anp + 1][0] = bt[2]; b[2 * anp + 1][1] = bt[3];
            }
            #pragma unroll
            for (int am = 0; am < 4; ++am)
                #pragma unroll
                for (int an = 0; an < 4; ++an)
                    hmma(acc[am][an], a[am], b[an][0], b[an][1]);
        }
        __syncthreads();
    }

    __half* Dh = FUSED ? ((z == 0) ? D0 : (z == 1) ? D1 : D2) : D0;
    const float qs = (FUSED && z == 0) ? CEXP : 1.f;   // fold softmax scale into Q
    #pragma unroll
    for (int am = 0; am < 4; ++am) {
        #pragma unroll
        for (int an = 0; an < 4; ++an) {
            const int r0 = bm + mw + 16 * am + lr;
            const int r1 = r0 + 8;
            const int c0 = bn + nw + 8 * an + lc2;
            float v0 = acc[am][an][0], v1 = acc[am][an][1];
            float v2 = acc[am][an][2], v3 = acc[am][an][3];
            if (FUSED) {   // head-split fp16 [b,h,t,d]
                v0 *= qs; v1 *= qs; v2 *= qs; v3 *= qs;
                const int h = c0 >> 6, d = c0 & 63;
                const int b0i = r0 >> 11, t0 = r0 & 2047;
                const int b1i = r1 >> 11, t1 = r1 & 2047;
                *(__half2*)&Dh[((size_t)((b0i * NHEAD + h) * SEQ + t0)) * HS + d] =
                    __floats2half2_rn(v0, v1);
                *(__half2*)&Dh[((size_t)((b1i * NHEAD + h) * SEQ + t1)) * HS + d] =
                    __floats2half2_rn(v2, v3);
            } else {       // fp32 + bias
                const float bb0 = bias[c0], bb1 = bias[c0 + 1];
                float2 o0 = make_float2(v0 + bb0, v1 + bb1);
                float2 o1 = make_float2(v2 + bb0, v3 + bb1);
                *(float2*)&Dout[(size_t)r0 * EMB + c0] = o0;
                *(float2*)&Dout[(size_t)r1 * EMB + c0] = o1;
            }
        }
    }
}

// ---------------- HMMA flash attention (round-9 proven) ----------------
// CTA: 128 queries x one (b,h). 256 threads (8 warps x 16 q-rows).
// 64-key tiles, cp.async double-buffered. Q pre-scaled by CEXP (exp = ex2(s)).
// Warps 0-3 skip the final all-masked tile; mask applies to exactly one tile/warp.
#define KSTR 72
#define ATTN_SMEM ((128 * KSTR + 2 * 64 * KSTR + 2 * 64 * KSTR) * 2)

__global__ __launch_bounds__(256)
void attn_hmma(const __half* __restrict__ Q, const __half* __restrict__ K,
               const __half* __restrict__ V, __half* __restrict__ O)
{
    extern __shared__ __align__(16) __half dsm[];
    __half (*Qs)[KSTR]     = (__half(*)[KSTR])dsm;
    __half (*Ks)[64][KSTR] = (__half(*)[64][KSTR])(dsm + 128 * KSTR);
    __half (*Vs)[64][KSTR] = (__half(*)[64][KSTR])(dsm + 128 * KSTR + 2 * 64 * KSTR);

    const int tid = threadIdx.x, wid = tid >> 5, lane = tid & 31;
    const int lr = lane >> 2, lc2 = 2 * (lane & 3);
    const int bh = blockIdx.y;
    const int qt = (gridDim.x - 1) - blockIdx.x;   // longest first
    const int q0 = qt * 128;
    const int NT = 2 * (qt + 1);

    const __half* Qb = Q + (size_t)bh * SEQ * HS;
    const __half* Kb = K + (size_t)bh * SEQ * HS;
    const __half* Vb = V + (size_t)bh * SEQ * HS;

    // stage Q: 128 rows x 64 halves; 4 chunks/thread
    {
        const int row = tid >> 1, cb4 = (tid & 1) * 4;
        #pragma unroll
        for (int i = 0; i < 4; i++)
            *(uint4*)&Qs[row][(cb4 + i) * 8] =
                *(const uint4*)(Qb + (size_t)(q0 + row) * HS + (cb4 + i) * 8);
    }
    const int krow = tid >> 2, kb2 = (tid & 3) * 2;
    {
        #pragma unroll
        for (int i = 0; i < 2; i++) {
            cp16(smem_u32(&Ks[0][krow][(kb2 + i) * 8]), Kb + (size_t)krow * HS + (kb2 + i) * 8);
            cp16(smem_u32(&Vs[0][krow][(kb2 + i) * 8]), Vb + (size_t)krow * HS + (kb2 + i) * 8);
        }
        CP_COMMIT();
    }
    __syncthreads();

    // Q fragments via ldmatrix
    uint32_t qa[4][4];
    {
        const int a_r = 16 * wid + (lane & 15), a_c = 8 * (lane >> 4);
        #pragma unroll
        for (int t = 0; t < 4; ++t)
            ldsm4(qa[t], smem_u32(&Qs[a_r][16 * t + a_c]));
    }

    float o[8][4];
    #pragma unroll
    for (int j = 0; j < 8; ++j)
        #pragma unroll
        for (int f = 0; f < 4; ++f) o[j][f] = 0.f;
    float rsacc[4] = {0.f, 0.f, 0.f, 0.f};
    const int gq0 = q0 + 16 * wid + lr;
    const int gq1 = gq0 + 8;
    const bool lowhalf = (wid < 4);    // query rows q0..q0+63

    const int nb_r = (lane & 7) + 8 * (lane >> 4), nb_c = 8 * ((lane >> 3) & 1);
    const int tb_r = (lane & 7) + 8 * ((lane >> 3) & 1), tb_c = 8 * (lane >> 4);

    for (int kt = 0; kt < NT; ++kt) {
        if (kt + 1 < NT) {
            const int nb = (kt + 1) & 1;
            const int k0n = (kt + 1) * 64;
            #pragma unroll
            for (int i = 0; i < 2; i++) {
                cp16(smem_u32(&Ks[nb][krow][(kb2 + i) * 8]),
                     Kb + (size_t)(k0n + krow) * HS + (kb2 + i) * 8);
                cp16(smem_u32(&Vs[nb][krow][(kb2 + i) * 8]),
                     Vb + (size_t)(k0n + krow) * HS + (kb2 + i) * 8);
            }
            CP_COMMIT();
            CP_WAIT1();
        } else {
            CP_WAIT0();
        }
        __syncthreads();

        // warps 0-3: final tile is entirely above the diagonal -> skip compute
        const bool skiptile = lowhalf && (kt == NT - 1);
        if (!skiptile) {
            const int cb = kt & 1;
            const int k0 = kt * 64;
            // exactly one tile per warp-half straddles the diagonal
            const bool domask = (kt == NT - (lowhalf ? 2 : 1));

            uint32_t pa[4][4];
            #pragma unroll
            for (int jp = 0; jp < 4; ++jp) {
                float s0[4] = {0.f, 0.f, 0.f, 0.f};
                float s1[4] = {0.f, 0.f, 0.f, 0.f};
                #pragma unroll
                for (int t = 0; t < 4; ++t) {
                    uint32_t kb[4];
                    ldsm4(kb, smem_u32(&Ks[cb][16 * jp + nb_r][16 * t + nb_c]));
                    hmma(s0, qa[t], kb[0], kb[1]);
                    hmma(s1, qa[t], kb[2], kb[3]);
                }
                float v00 = s0[0], v01 = s0[1], v02 = s0[2], v03 = s0[3];
                float v10 = s1[0], v11 = s1[1], v12 = s1[2], v13 = s1[3];
                if (domask) {
                    const int keyb = k0 + 16 * jp + lc2;
                    v00 = (keyb     <= gq0) ? v00 : -1e4f;
                    v01 = (keyb + 1 <= gq0) ? v01 : -1e4f;
                    v02 = (keyb     <= gq1) ? v02 : -1e4f;
                    v03 = (keyb + 1 <= gq1) ? v03 : -1e4f;
                    v10 = (keyb + 8 <= gq0) ? v10 : -1e4f;
                    v11 = (keyb + 9 <= gq0) ? v11 : -1e4f;
                    v12 = (keyb + 8 <= gq1) ? v12 : -1e4f;
                    v13 = (keyb + 9 <= gq1) ? v13 : -1e4f;
                }
                pa[jp][0] = h2exp2(pack2(v00, v01));
                pa[jp][1] = h2exp2(pack2(v02, v03));
                pa[jp][2] = h2exp2(pack2(v10, v11));
                pa[jp][3] = h2exp2(pack2(v12, v13));
                hmma(rsacc, pa[jp], ONES2, ONES2);   // row sums
            }
            #pragma unroll
            for (int dp = 0; dp < 4; ++dp) {
                #pragma unroll
                for (int t = 0; t < 4; ++t) {
                    uint32_t vbf[4];
                    ldsm4t(vbf, smem_u32(&Vs[cb][16 * t + tb_r][16 * dp + tb_c]));
                    hmma(o[2 * dp],     pa[t], vbf[0], vbf[1]);
                    hmma(o[2 * dp + 1], pa[t], vbf[2], vbf[3]);
                }
            }
        }
        __syncthreads();
    }

    const float inv0 = 1.f / rsacc[0], inv1 = 1.f / rsacc[2];
    const int b = bh >> 4, h = bh & 15;
    __half* d0 = O + ((size_t)(b * SEQ + gq0)) * EMB + h * HS;
    __half* d1 = O + ((size_t)(b * SEQ + gq1)) * EMB + h * HS;
    #pragma unroll
    for (int j = 0; j < 8; ++j) {
        const int d = 8 * j + lc2;
        *(__half2*)(d0 + d) = __floats2half2_rn(o[j][0] * inv0, o[j][1] * inv0);
        *(__half2*)(d1 + d) = __floats2half2_rn(o[j][2] * inv1, o[j][3] * inv1);
    }
}

// ---------------- launch ----------------
extern "C" void kernel_launch(void* const* d_in, const int* in_sizes, int n_in,
                              void* d_out, int out_size)
{
    const float* x  = (const float*)d_in[0];
    const float* Wq = (const float*)d_in[1];
    const float* Wk = (const float*)d_in[2];
    const float* Wv = (const float*)d_in[3];
    const float* Wp = (const float*)d_in[4];
    const float* bp = (const float*)d_in[5];
    float* out = (float*)d_out;

    __half *xh, *wq, *wk, *wv, *wp, *qh, *kh, *vh, *ah;
    cudaGetSymbolAddress((void**)&xh, g_xh);
    cudaGetSymbolAddress((void**)&wq, g_Wqh);
    cudaGetSymbolAddress((void**)&wk, g_Wkh);
    cudaGetSymbolAddress((void**)&wv, g_Wvh);
    cudaGetSymbolAddress((void**)&wp, g_Wph);
    cudaGetSymbolAddress((void**)&qh, g_Qh);
    cudaGetSymbolAddress((void**)&kh, g_Kh);
    cudaGetSymbolAddress((void**)&vh, g_Vh);
    cudaGetSymbolAddress((void**)&ah, g_Ah);

    cudaFuncSetAttribute(attn_hmma, cudaFuncAttributeMaxDynamicSharedMemorySize, ATTN_SMEM);

    cvt_all_kernel<<<XF4 / 256, 256>>>(x, Wq, Wk, Wv, Wp, xh, wq, wk, wv, wp);

    gemm_hmma<1><<<dim3(EMB / 128, MROWS / 128, 3), 256>>>(
        xh, wq, wk, wv, qh, kh, vh, nullptr, nullptr);

    attn_hmma<<<dim3(SEQ / 128, BATCH * NHEAD), 256, ATTN_SMEM>>>(qh, kh, vh, ah);

    gemm_hmma<0><<<dim3(EMB / 128, MROWS / 128, 1), 256>>>(
        ah, wp, nullptr, nullptr, nullptr, nullptr, nullptr, out, bp);
}

// round 11
// speedup vs baseline: 1.0547x; 1.0547x over previous
#include <cuda_runtime.h>
#include <cuda_fp16.h>
#include <cstdint>

#define BATCH 2
#define SEQ   2048
#define EMB   1024
#define NHEAD 16
#define HS    64
#define MROWS 4096
// exp(s/32) = 2^(s * CEXP), folded into Q at projection time
#define CEXP  0.045084294f

// ---------------- scratch (device globals) ----------------
__device__ __half g_xh[MROWS * EMB];
__device__ __half g_Wqh[EMB * EMB];   // fp16, K-major [k][n]
__device__ __half g_Wkh[EMB * EMB];
__device__ __half g_Wvh[EMB * EMB];
__device__ __half g_Wph[EMB * EMB];
__device__ __half g_Qh[MROWS * EMB];  // [b,h,t,d], pre-scaled by CEXP
__device__ __half g_Kh[MROWS * EMB];  // [b,h,t,d]
__device__ __half g_Vh[MROWS * EMB];  // [b,h,t,d]
__device__ __half g_Ah[MROWS * EMB];  // [b*t, h*64+d]

// ---------------- helpers ----------------
__device__ __forceinline__ uint32_t smem_u32(const void* p) {
    uint32_t a;
    asm("{ .reg .u64 t; cvta.to.shared.u64 t, %1; cvt.u32.u64 %0, t; }" : "=r"(a) : "l"(p));
    return a;
}
__device__ __forceinline__ void cp16(uint32_t saddr, const void* g) {
    asm volatile("cp.async.cg.shared.global [%0], [%1], 16;" :: "r"(saddr), "l"(g));
}
#define CP_COMMIT() asm volatile("cp.async.commit_group;" ::: "memory")
#define CP_WAIT0()  asm volatile("cp.async.wait_group 0;" ::: "memory")
#define CP_WAIT1()  asm volatile("cp.async.wait_group 1;" ::: "memory")

__device__ __forceinline__ void hmma(float* c, const uint32_t* a, uint32_t b0, uint32_t b1) {
    asm volatile("mma.sync.aligned.m16n8k16.row.col.f32.f16.f16.f32 "
        "{%0,%1,%2,%3}, {%4,%5,%6,%7}, {%8,%9}, {%0,%1,%2,%3};"
        : "+f"(c[0]), "+f"(c[1]), "+f"(c[2]), "+f"(c[3])
        : "r"(a[0]), "r"(a[1]), "r"(a[2]), "r"(a[3]), "r"(b0), "r"(b1));
}
__device__ __forceinline__ void ldsm4(uint32_t* r, uint32_t addr) {
    asm volatile("ldmatrix.sync.aligned.m8n8.x4.shared.b16 {%0,%1,%2,%3}, [%4];"
        : "=r"(r[0]), "=r"(r[1]), "=r"(r[2]), "=r"(r[3]) : "r"(addr));
}
__device__ __forceinline__ void ldsm4t(uint32_t* r, uint32_t addr) {
    asm volatile("ldmatrix.sync.aligned.m8n8.x4.trans.shared.b16 {%0,%1,%2,%3}, [%4];"
        : "=r"(r[0]), "=r"(r[1]), "=r"(r[2]), "=r"(r[3]) : "r"(addr));
}
__device__ __forceinline__ uint32_t pack2(float a, float b) {
    __half2 h = __floats2half2_rn(a, b);
    return *(uint32_t*)&h;
}
__device__ __forceinline__ uint32_t h2exp2(uint32_t x) {
    uint32_t r;
    asm("ex2.approx.f16x2 %0, %1;" : "=r"(r) : "r"(x));
    return r;
}
#define ONES2 0x3C003C00u   // half2(1, 1)

// ---------------- fused conversion: x + 4 weights, one kernel ----------------
#define XF4 (MROWS * EMB / 4)          // 1048576
#define WF4 (EMB * EMB / 4)            // 262144

__global__ __launch_bounds__(256)
void cvt_all_kernel(const float* __restrict__ x,
                    const float* __restrict__ Wq, const float* __restrict__ Wk,
                    const float* __restrict__ Wv, const float* __restrict__ Wp,
                    __half* __restrict__ xh,
                    __half* __restrict__ wq, __half* __restrict__ wk,
                    __half* __restrict__ wv, __half* __restrict__ wp)
{
    const int base = blockIdx.x * 256 + threadIdx.x;
    #pragma unroll
    for (int j = 0; j < 2; ++j) {
        int idx = base + j * XF4;      // covers [0, 2M)
        const float* src;
        __half* dst;
        int off;
        if (idx < XF4)                { src = x;  dst = xh; off = idx; }
        else if (idx < XF4 + WF4)     { src = Wq; dst = wq; off = idx - XF4; }
        else if (idx < XF4 + 2 * WF4) { src = Wk; dst = wk; off = idx - XF4 - WF4; }
        else if (idx < XF4 + 3 * WF4) { src = Wv; dst = wv; off = idx - XF4 - 2 * WF4; }
        else                          { src = Wp; dst = wp; off = idx - XF4 - 3 * WF4; }
        float4 v = *(const float4*)(src + (size_t)off * 4);
        *(__half2*)(dst + (size_t)off * 4)     = __floats2half2_rn(v.x, v.y);
        *(__half2*)(dst + (size_t)off * 4 + 2) = __floats2half2_rn(v.z, v.w);
    }
}

// ---------------- HMMA GEMM: C[M,N] = A[M,K] * B[K,N] ----------------
// CTA tile 128x256, warp tile 64x64 (8 warps, 2x4), BK=32,
// 3-stage cp.async ring, ONE __syncthreads per k-tile.
#define ASTR 40    // A smem stride (32 + 8 pad halves)
#define BSTR 264   // B smem stride (256 + 8 pad halves)
#define ABUF (128 * ASTR)              // halves per A stage
#define BBUF (32 * BSTR)               // halves per B stage
#define GSMEM (3 * (ABUF + BBUF) * 2)  // 81408 B

template <int FUSED>
__global__ __launch_bounds__(256)
void gemm_hmma(const __half* __restrict__ A,
               const __half* __restrict__ B0, const __half* __restrict__ B1,
               const __half* __restrict__ B2,
               __half* __restrict__ D0, __half* __restrict__ D1,
               __half* __restrict__ D2,
               float* __restrict__ Dout, const float* __restrict__ bias)
{
    extern __shared__ __align__(16) __half gsm[];

    const int tid = threadIdx.x, wid = tid >> 5, lane = tid & 31;
    const int bn = blockIdx.x * 256, bm = blockIdx.y * 128;
    const int z = FUSED ? blockIdx.z : 0;
    const __half* B = FUSED ? ((z == 0) ? B0 : (z == 1) ? B1 : B2) : B0;
    const int mw = (wid & 1) * 64, nw = (wid >> 1) * 64;
    const int lr = lane >> 2, lc2 = 2 * (lane & 3);

    float acc[4][8][4];
    #pragma unroll
    for (int i = 0; i < 4; i++)
        #pragma unroll
        for (int j = 0; j < 8; j++)
            #pragma unroll
            for (int f = 0; f < 4; f++) acc[i][j][f] = 0.f;

    // A staging: 128 rows x 4 chunks = 512 chunks; 2/thread
    const int arow = tid >> 1, acb = (tid & 1) * 2;

    auto stage = [&](int s, int k0) {
        __half (*as)[ASTR] = (__half(*)[ASTR])(gsm + (size_t)s * ABUF);
        __half (*bs)[BSTR] = (__half(*)[BSTR])(gsm + 3 * ABUF + (size_t)s * BBUF);
        const __half* Ag = A + (size_t)(bm + arow) * EMB + k0;
        #pragma unroll
        for (int i = 0; i < 2; i++)
            cp16(smem_u32(&as[arow][(acb + i) * 8]), Ag + (acb + i) * 8);
        // B staging: 32 rows x 32 chunks = 1024 chunks; 4/thread
        #pragma unroll
        for (int i = 0; i < 4; i++) {
            const int lin = tid + i * 256;
            const int brow = lin >> 5, bcc = lin & 31;
            cp16(smem_u32(&bs[brow][bcc * 8]), B + (size_t)(k0 + brow) * EMB + bn + bcc * 8);
        }
        CP_COMMIT();
    };

    stage(0, 0);
    stage(1, 32);

    const int a_r = lane & 15, a_c = 8 * (lane >> 4);
    const int b_r = (lane & 7) + 8 * ((lane >> 3) & 1), b_c = 8 * (lane >> 4);

    for (int kt = 0; kt < 32; ++kt) {
        if (kt + 1 < 32) CP_WAIT1(); else CP_WAIT0();
        __syncthreads();                       // all warps done with kt-1 compute
        if (kt + 2 < 32) stage((kt + 2) % 3, (kt + 2) * 32);

        const int cb = kt % 3;
        __half (*As)[ASTR] = (__half(*)[ASTR])(gsm + (size_t)cb * ABUF);
        __half (*Bs)[BSTR] = (__half(*)[BSTR])(gsm + 3 * ABUF + (size_t)cb * BBUF);
        #pragma unroll
        for (int kk = 0; kk < 2; ++kk) {
            uint32_t a[4][4], b[8][2];
            #pragma unroll
            for (int am = 0; am < 4; ++am)
                ldsm4(a[am], smem_u32(&As[mw + 16 * am + a_r][16 * kk + a_c]));
            #pragma unroll
            for (int anp = 0; anp < 4; ++anp) {
                uint32_t bt[4];
                ldsm4t(bt, smem_u32(&Bs[16 * kk + b_r][nw + 16 * anp + b_c]));
                b[2 * anp][0] = bt[0]; b[2 * anp][1] = bt[1];
                b[2 * anp + 1][0] = bt[2]; b[2 * anp + 1][1] = bt[3];
            }
            #pragma unroll
            for (int am = 0; am < 4; ++am)
                #pragma unroll
                for (int an = 0; an < 8; ++an)
                    hmma(acc[am][an], a[am], b[an][0], b[an][1]);
        }
    }

    __syncthreads();   // protect last stage (not strictly needed; cheap)

    __half* Dh = FUSED ? ((z == 0) ? D0 : (z == 1) ? D1 : D2) : D0;
    const float qs = (FUSED && z == 0) ? CEXP : 1.f;   // fold softmax scale into Q
    #pragma unroll
    for (int am = 0; am < 4; ++am) {
        #pragma unroll
        for (int an = 0; an < 8; ++an) {
            const int r0 = bm + mw + 16 * am + lr;
            const int r1 = r0 + 8;
            const int c0 = bn + nw + 8 * an + lc2;
            float v0 = acc[am][an][0], v1 = acc[am][an][1];
            float v2 = acc[am][an][2], v3 = acc[am][an][3];
            if (FUSED) {   // head-split fp16 [b,h,t,d]
                v0 *= qs; v1 *= qs; v2 *= qs; v3 *= qs;
                const int h = c0 >> 6, d = c0 & 63;
                const int b0i = r0 >> 11, t0 = r0 & 2047;
                const int b1i = r1 >> 11, t1 = r1 & 2047;
                *(__half2*)&Dh[((size_t)((b0i * NHEAD + h) * SEQ + t0)) * HS + d] =
                    __floats2half2_rn(v0, v1);
                *(__half2*)&Dh[((size_t)((b1i * NHEAD + h) * SEQ + t1)) * HS + d] =
                    __floats2half2_rn(v2, v3);
            } else {       // fp32 + bias
                const float bb0 = bias[c0], bb1 = bias[c0 + 1];
                float2 o0 = make_float2(v0 + bb0, v1 + bb1);
                float2 o1 = make_float2(v2 + bb0, v3 + bb1);
                *(float2*)&Dout[(size_t)r0 * EMB + c0] = o0;
                *(float2*)&Dout[(size_t)r1 * EMB + c0] = o1;
            }
        }
    }
}

// ---------------- HMMA flash attention (round-9 proven, untouched) ----------
#define KSTR 72
#define ATTN_SMEM ((128 * KSTR + 2 * 64 * KSTR + 2 * 64 * KSTR) * 2)

__global__ __launch_bounds__(256)
void attn_hmma(const __half* __restrict__ Q, const __half* __restrict__ K,
               const __half* __restrict__ V, __half* __restrict__ O)
{
    extern __shared__ __align__(16) __half dsm[];
    __half (*Qs)[KSTR]     = (__half(*)[KSTR])dsm;
    __half (*Ks)[64][KSTR] = (__half(*)[64][KSTR])(dsm + 128 * KSTR);
    __half (*Vs)[64][KSTR] = (__half(*)[64][KSTR])(dsm + 128 * KSTR + 2 * 64 * KSTR);

    const int tid = threadIdx.x, wid = tid >> 5, lane = tid & 31;
    const int lr = lane >> 2, lc2 = 2 * (lane & 3);
    const int bh = blockIdx.y;
    const int qt = (gridDim.x - 1) - blockIdx.x;   // longest first
    const int q0 = qt * 128;
    const int NT = 2 * (qt + 1);

    const __half* Qb = Q + (size_t)bh * SEQ * HS;
    const __half* Kb = K + (size_t)bh * SEQ * HS;
    const __half* Vb = V + (size_t)bh * SEQ * HS;

    {
        const int row = tid >> 1, cb4 = (tid & 1) * 4;
        #pragma unroll
        for (int i = 0; i < 4; i++)
            *(uint4*)&Qs[row][(cb4 + i) * 8] =
                *(const uint4*)(Qb + (size_t)(q0 + row) * HS + (cb4 + i) * 8);
    }
    const int krow = tid >> 2, kb2 = (tid & 3) * 2;
    {
        #pragma unroll
        for (int i = 0; i < 2; i++) {
            cp16(smem_u32(&Ks[0][krow][(kb2 + i) * 8]), Kb + (size_t)krow * HS + (kb2 + i) * 8);
            cp16(smem_u32(&Vs[0][krow][(kb2 + i) * 8]), Vb + (size_t)krow * HS + (kb2 + i) * 8);
        }
        CP_COMMIT();
    }
    __syncthreads();

    uint32_t qa[4][4];
    {
        const int a_r = 16 * wid + (lane & 15), a_c = 8 * (lane >> 4);
        #pragma unroll
        for (int t = 0; t < 4; ++t)
            ldsm4(qa[t], smem_u32(&Qs[a_r][16 * t + a_c]));
    }

    float o[8][4];
    #pragma unroll
    for (int j = 0; j < 8; ++j)
        #pragma unroll
        for (int f = 0; f < 4; ++f) o[j][f] = 0.f;
    float rsacc[4] = {0.f, 0.f, 0.f, 0.f};
    const int gq0 = q0 + 16 * wid + lr;
    const int gq1 = gq0 + 8;
    const bool lowhalf = (wid < 4);

    const int nb_r = (lane & 7) + 8 * (lane >> 4), nb_c = 8 * ((lane >> 3) & 1);
    const int tb_r = (lane & 7) + 8 * ((lane >> 3) & 1), tb_c = 8 * (lane >> 4);

    for (int kt = 0; kt < NT; ++kt) {
        if (kt + 1 < NT) {
            const int nb = (kt + 1) & 1;
            const int k0n = (kt + 1) * 64;
            #pragma unroll
            for (int i = 0; i < 2; i++) {
                cp16(smem_u32(&Ks[nb][krow][(kb2 + i) * 8]),
                     Kb + (size_t)(k0n + krow) * HS + (kb2 + i) * 8);
                cp16(smem_u32(&Vs[nb][krow][(kb2 + i) * 8]),
                     Vb + (size_t)(k0n + krow) * HS + (kb2 + i) * 8);
            }
            CP_COMMIT();
            CP_WAIT1();
        } else {
            CP_WAIT0();
        }
        __syncthreads();

        const bool skiptile = lowhalf && (kt == NT - 1);
        if (!skiptile) {
            const int cb = kt & 1;
            const int k0 = kt * 64;
            const bool domask = (kt == NT - (lowhalf ? 2 : 1));

            uint32_t pa[4][4];
            #pragma unroll
            for (int jp = 0; jp < 4; ++jp) {
                float s0[4] = {0.f, 0.f, 0.f, 0.f};
                float s1[4] = {0.f, 0.f, 0.f, 0.f};
                #pragma unroll
                for (int t = 0; t < 4; ++t) {
                    uint32_t kb[4];
                    ldsm4(kb, smem_u32(&Ks[cb][16 * jp + nb_r][16 * t + nb_c]));
                    hmma(s0, qa[t], kb[0], kb[1]);
                    hmma(s1, qa[t], kb[2], kb[3]);
                }
                float v00 = s0[0], v01 = s0[1], v02 = s0[2], v03 = s0[3];
                float v10 = s1[0], v11 = s1[1], v12 = s1[2], v13 = s1[3];
                if (domask) {
                    const int keyb = k0 + 16 * jp + lc2;
                    v00 = (keyb     <= gq0) ? v00 : -1e4f;
                    v01 = (keyb + 1 <= gq0) ? v01 : -1e4f;
                    v02 = (keyb     <= gq1) ? v02 : -1e4f;
                    v03 = (keyb + 1 <= gq1) ? v03 : -1e4f;
                    v10 = (keyb + 8 <= gq0) ? v10 : -1e4f;
                    v11 = (keyb + 9 <= gq0) ? v11 : -1e4f;
                    v12 = (keyb + 8 <= gq1) ? v12 : -1e4f;
                    v13 = (keyb + 9 <= gq1) ? v13 : -1e4f;
                }
                pa[jp][0] = h2exp2(pack2(v00, v01));
                pa[jp][1] = h2exp2(pack2(v02, v03));
                pa[jp][2] = h2exp2(pack2(v10, v11));
                pa[jp][3] = h2exp2(pack2(v12, v13));
                hmma(rsacc, pa[jp], ONES2, ONES2);
            }
            #pragma unroll
            for (int dp = 0; dp < 4; ++dp) {
                #pragma unroll
                for (int t = 0; t < 4; ++t) {
                    uint32_t vbf[4];
                    ldsm4t(vbf, smem_u32(&Vs[cb][16 * t + tb_r][16 * dp + tb_c]));
                    hmma(o[2 * dp],     pa[t], vbf[0], vbf[1]);
                    hmma(o[2 * dp + 1], pa[t], vbf[2], vbf[3]);
                }
            }
        }
        __syncthreads();
    }

    const float inv0 = 1.f / rsacc[0], inv1 = 1.f / rsacc[2];
    const int b = bh >> 4, h = bh & 15;
    __half* d0 = O + ((size_t)(b * SEQ + gq0)) * EMB + h * HS;
    __half* d1 = O + ((size_t)(b * SEQ + gq1)) * EMB + h * HS;
    #pragma unroll
    for (int j = 0; j < 8; ++j) {
        const int d = 8 * j + lc2;
        *(__half2*)(d0 + d) = __floats2half2_rn(o[j][0] * inv0, o[j][1] * inv0);
        *(__half2*)(d1 + d) = __floats2half2_rn(o[j][2] * inv1, o[j][3] * inv1);
    }
}

// ---------------- launch ----------------
extern "C" void kernel_launch(void* const* d_in, const int* in_sizes, int n_in,
                              void* d_out, int out_size)
{
    const float* x  = (const float*)d_in[0];
    const float* Wq = (const float*)d_in[1];
    const float* Wk = (const float*)d_in[2];
    const float* Wv = (const float*)d_in[3];
    const float* Wp = (const float*)d_in[4];
    const float* bp = (const float*)d_in[5];
    float* out = (float*)d_out;

    __half *xh, *wq, *wk, *wv, *wp, *qh, *kh, *vh, *ah;
    cudaGetSymbolAddress((void**)&xh, g_xh);
    cudaGetSymbolAddress((void**)&wq, g_Wqh);
    cudaGetSymbolAddress((void**)&wk, g_Wkh);
    cudaGetSymbolAddress((void**)&wv, g_Wvh);
    cudaGetSymbolAddress((void**)&wp, g_Wph);
    cudaGetSymbolAddress((void**)&qh, g_Qh);
    cudaGetSymbolAddress((void**)&kh, g_Kh);
    cudaGetSymbolAddress((void**)&vh, g_Vh);
    cudaGetSymbolAddress((void**)&ah, g_Ah);

    cudaFuncSetAttribute(gemm_hmma<1>, cudaFuncAttributeMaxDynamicSharedMemorySize, GSMEM);
    cudaFuncSetAttribute(gemm_hmma<0>, cudaFuncAttributeMaxDynamicSharedMemorySize, GSMEM);
    cudaFuncSetAttribute(attn_hmma, cudaFuncAttributeMaxDynamicSharedMemorySize, ATTN_SMEM);

    cvt_all_kernel<<<XF4 / 256, 256>>>(x, Wq, Wk, Wv, Wp, xh, wq, wk, wv, wp);

    gemm_hmma<1><<<dim3(EMB / 256, MROWS / 128, 3), 256, GSMEM>>>(
        xh, wq, wk, wv, qh, kh, vh, nullptr, nullptr);

    attn_hmma<<<dim3(SEQ / 128, BATCH * NHEAD), 256, ATTN_SMEM>>>(qh, kh, vh, ah);

    gemm_hmma<0><<<dim3(EMB / 256, MROWS / 128, 1), 256, GSMEM>>>(
        ah, wp, nullptr, nullptr, nullptr, nullptr, nullptr, out, bp);
}

// round 12
// speedup vs baseline: 1.1051x; 1.0479x over previous
#include <cuda_runtime.h>
#include <cuda_fp16.h>
#include <cstdint>

#define BATCH 2
#define SEQ   2048
#define EMB   1024
#define NHEAD 16
#define HS    64
#define MROWS 4096
// exp(s/32) = 2^(s * CEXP), folded into Q at projection time
#define CEXP  0.045084294f

// ---------------- scratch (device globals) ----------------
__device__ __half g_xh[MROWS * EMB];
__device__ __half g_Wqh[EMB * EMB];   // fp16, K-major [k][n]
__device__ __half g_Wkh[EMB * EMB];
__device__ __half g_Wvh[EMB * EMB];
__device__ __half g_Wph[EMB * EMB];
__device__ __half g_Qh[MROWS * EMB];  // [b,h,t,d], pre-scaled by CEXP
__device__ __half g_Kh[MROWS * EMB];  // [b,h,t,d]
__device__ __half g_Vh[MROWS * EMB];  // [b,h,t,d]
__device__ __half g_Ah[MROWS * EMB];  // [b*t, h*64+d]

// ---------------- helpers ----------------
__device__ __forceinline__ uint32_t smem_u32(const void* p) {
    uint32_t a;
    asm("{ .reg .u64 t; cvta.to.shared.u64 t, %1; cvt.u32.u64 %0, t; }" : "=r"(a) : "l"(p));
    return a;
}
__device__ __forceinline__ void cp16(uint32_t saddr, const void* g) {
    asm volatile("cp.async.cg.shared.global [%0], [%1], 16;" :: "r"(saddr), "l"(g));
}
#define CP_COMMIT() asm volatile("cp.async.commit_group;" ::: "memory")
#define CP_WAIT0()  asm volatile("cp.async.wait_group 0;" ::: "memory")
#define CP_WAIT1()  asm volatile("cp.async.wait_group 1;" ::: "memory")

__device__ __forceinline__ void hmma(float* c, const uint32_t* a, uint32_t b0, uint32_t b1) {
    asm volatile("mma.sync.aligned.m16n8k16.row.col.f32.f16.f16.f32 "
        "{%0,%1,%2,%3}, {%4,%5,%6,%7}, {%8,%9}, {%0,%1,%2,%3};"
        : "+f"(c[0]), "+f"(c[1]), "+f"(c[2]), "+f"(c[3])
        : "r"(a[0]), "r"(a[1]), "r"(a[2]), "r"(a[3]), "r"(b0), "r"(b1));
}
__device__ __forceinline__ void ldsm4(uint32_t* r, uint32_t addr) {
    asm volatile("ldmatrix.sync.aligned.m8n8.x4.shared.b16 {%0,%1,%2,%3}, [%4];"
        : "=r"(r[0]), "=r"(r[1]), "=r"(r[2]), "=r"(r[3]) : "r"(addr));
}
__device__ __forceinline__ void ldsm4t(uint32_t* r, uint32_t addr) {
    asm volatile("ldmatrix.sync.aligned.m8n8.x4.trans.shared.b16 {%0,%1,%2,%3}, [%4];"
        : "=r"(r[0]), "=r"(r[1]), "=r"(r[2]), "=r"(r[3]) : "r"(addr));
}
__device__ __forceinline__ uint32_t pack2(float a, float b) {
    __half2 h = __floats2half2_rn(a, b);
    return *(uint32_t*)&h;
}
__device__ __forceinline__ uint32_t h2exp2(uint32_t x) {
    uint32_t r;
    asm("ex2.approx.f16x2 %0, %1;" : "=r"(r) : "r"(x));
    return r;
}
#define ONES2 0x3C003C00u   // half2(1, 1)

// ---------------- conversion kernels (round-5 proven) ----------------
__global__ __launch_bounds__(256) void cvt_x_kernel(const float* __restrict__ x,
                                                    __half* __restrict__ xh) {
    int i = (blockIdx.x * 256 + threadIdx.x) * 4;
    float4 v = *(const float4*)(x + i);
    *(__half2*)(xh + i)     = __floats2half2_rn(v.x, v.y);
    *(__half2*)(xh + i + 2) = __floats2half2_rn(v.z, v.w);
}

__global__ __launch_bounds__(256) void cvt_w_kernel(
    const float* __restrict__ W0, const float* __restrict__ W1,
    const float* __restrict__ W2, const float* __restrict__ W3,
    __half* __restrict__ D0, __half* __restrict__ D1,
    __half* __restrict__ D2, __half* __restrict__ D3)
{
    const int z = blockIdx.y;
    const float* W = (z == 0) ? W0 : (z == 1) ? W1 : (z == 2) ? W2 : W3;
    __half* D = (z == 0) ? D0 : (z == 1) ? D1 : (z == 2) ? D2 : D3;
    int i = (blockIdx.x * 256 + threadIdx.x) * 4;
    float4 v = *(const float4*)(W + i);
    *(__half2*)(D + i)     = __floats2half2_rn(v.x, v.y);
    *(__half2*)(D + i + 2) = __floats2half2_rn(v.z, v.w);
}

// ---------------- HMMA GEMM: C[M,N] = A[M,K] * B[K,N] ----------------
// 128x128 tile, BK=32, 256 threads (8 warps, 64x32 warp tiles).
// 3-stage cp.async ring, ONE __syncthreads per k-tile.
#define ASTR 40    // A smem stride (32 + 8 pad halves)
#define BSTR 136   // B smem stride (128 + 8 pad halves)
#define ABUF (128 * ASTR)              // 5120 halves per A stage
#define BBUF (32 * BSTR)               // 4352 halves per B stage
#define GSMEM (3 * (ABUF + BBUF) * 2)  // 56832 B

template <int FUSED>
__global__ __launch_bounds__(256, 2)
void gemm_hmma(const __half* __restrict__ A,
               const __half* __restrict__ B0, const __half* __restrict__ B1,
               const __half* __restrict__ B2,
               __half* __restrict__ D0, __half* __restrict__ D1,
               __half* __restrict__ D2,
               float* __restrict__ Dout, const float* __restrict__ bias)
{
    extern __shared__ __align__(16) __half gsm[];

    const int tid = threadIdx.x, wid = tid >> 5, lane = tid & 31;
    const int bn = blockIdx.x * 128, bm = blockIdx.y * 128;
    const int z = FUSED ? blockIdx.z : 0;
    const __half* B = FUSED ? ((z == 0) ? B0 : (z == 1) ? B1 : B2) : B0;
    const int mw = (wid & 1) * 64, nw = (wid >> 1) * 32;
    const int lr = lane >> 2, lc2 = 2 * (lane & 3);

    float acc[4][4][4];
    #pragma unroll
    for (int i = 0; i < 4; i++)
        #pragma unroll
        for (int j = 0; j < 4; j++)
            #pragma unroll
            for (int f = 0; f < 4; f++) acc[i][j][f] = 0.f;

    const int arow = tid >> 1, acb = (tid & 1) * 2;
    const int br0 = tid >> 4, bc0 = tid & 15;
    const int br1 = (tid + 256) >> 4, bc1 = bc0;

    auto stage = [&](int s, int k0) {
        __half (*as)[ASTR] = (__half(*)[ASTR])(gsm + (size_t)s * ABUF);
        __half (*bs)[BSTR] = (__half(*)[BSTR])(gsm + 3 * ABUF + (size_t)s * BBUF);
        const __half* Ag = A + (size_t)(bm + arow) * EMB + k0;
        #pragma unroll
        for (int i = 0; i < 2; i++)
            cp16(smem_u32(&as[arow][(acb + i) * 8]), Ag + (acb + i) * 8);
        cp16(smem_u32(&bs[br0][bc0 * 8]), B + (size_t)(k0 + br0) * EMB + bn + bc0 * 8);
        cp16(smem_u32(&bs[br1][bc1 * 8]), B + (size_t)(k0 + br1) * EMB + bn + bc1 * 8);
        CP_COMMIT();
    };

    stage(0, 0);
    stage(1, 32);

    const int a_r = lane & 15, a_c = 8 * (lane >> 4);
    const int b_r = (lane & 7) + 8 * ((lane >> 3) & 1), b_c = 8 * (lane >> 4);

    for (int kt = 0; kt < 32; ++kt) {
        if (kt + 1 < 32) CP_WAIT1(); else CP_WAIT0();
        __syncthreads();                       // all warps done with kt-1 compute
        if (kt + 2 < 32) stage((kt + 2) % 3, (kt + 2) * 32);

        const int cb = kt % 3;
        __half (*As)[ASTR] = (__half(*)[ASTR])(gsm + (size_t)cb * ABUF);
        __half (*Bs)[BSTR] = (__half(*)[BSTR])(gsm + 3 * ABUF + (size_t)cb * BBUF);
        #pragma unroll
        for (int kk = 0; kk < 2; ++kk) {
            uint32_t a[4][4], b[4][2];
            #pragma unroll
            for (int am = 0; am < 4; ++am)
                ldsm4(a[am], smem_u32(&As[mw + 16 * am + a_r][16 * kk + a_c]));
            #pragma unroll
            for (int anp = 0; anp < 2; ++anp) {
                uint32_t bt[4];
                ldsm4t(bt, smem_u32(&Bs[16 * kk + b_r][nw + 16 * anp + b_c]));
                b[2 * anp][0] = bt[0]; b[2 * anp][1] = bt[1];
                b[2 * anp + 1][0] = bt[2]; b[2 * anp + 1][1] = bt[3];
            }
            #pragma unroll
            for (int am = 0; am < 4; ++am)
                #pragma unroll
                for (int an = 0; an < 4; ++an)
                    hmma(acc[am][an], a[am], b[an][0], b[an][1]);
        }
    }

    __half* Dh = FUSED ? ((z == 0) ? D0 : (z == 1) ? D1 : D2) : D0;
    const float qs = (FUSED && z == 0) ? CEXP : 1.f;   // fold softmax scale into Q
    #pragma unroll
    for (int am = 0; am < 4; ++am) {
        #pragma unroll
        for (int an = 0; an < 4; ++an) {
            const int r0 = bm + mw + 16 * am + lr;
            const int r1 = r0 + 8;
            const int c0 = bn + nw + 8 * an + lc2;
            float v0 = acc[am][an][0], v1 = acc[am][an][1];
            float v2 = acc[am][an][2], v3 = acc[am][an][3];
            if (FUSED) {   // head-split fp16 [b,h,t,d]
                v0 *= qs; v1 *= qs; v2 *= qs; v3 *= qs;
                const int h = c0 >> 6, d = c0 & 63;
                const int b0i = r0 >> 11, t0 = r0 & 2047;
                const int b1i = r1 >> 11, t1 = r1 & 2047;
                *(__half2*)&Dh[((size_t)((b0i * NHEAD + h) * SEQ + t0)) * HS + d] =
                    __floats2half2_rn(v0, v1);
                *(__half2*)&Dh[((size_t)((b1i * NHEAD + h) * SEQ + t1)) * HS + d] =
                    __floats2half2_rn(v2, v3);
            } else {       // fp32 + bias
                const float bb0 = bias[c0], bb1 = bias[c0 + 1];
                float2 o0 = make_float2(v0 + bb0, v1 + bb1);
                float2 o1 = make_float2(v2 + bb0, v3 + bb1);
                *(float2*)&Dout[(size_t)r0 * EMB + c0] = o0;
                *(float2*)&Dout[(size_t)r1 * EMB + c0] = o1;
            }
        }
    }
}

// ---------------- HMMA flash attention (round-9 proven, untouched) ----------
#define KSTR 72
#define ATTN_SMEM ((128 * KSTR + 2 * 64 * KSTR + 2 * 64 * KSTR) * 2)

__global__ __launch_bounds__(256)
void attn_hmma(const __half* __restrict__ Q, const __half* __restrict__ K,
               const __half* __restrict__ V, __half* __restrict__ O)
{
    extern __shared__ __align__(16) __half dsm[];
    __half (*Qs)[KSTR]     = (__half(*)[KSTR])dsm;
    __half (*Ks)[64][KSTR] = (__half(*)[64][KSTR])(dsm + 128 * KSTR);
    __half (*Vs)[64][KSTR] = (__half(*)[64][KSTR])(dsm + 128 * KSTR + 2 * 64 * KSTR);

    const int tid = threadIdx.x, wid = tid >> 5, lane = tid & 31;
    const int lr = lane >> 2, lc2 = 2 * (lane & 3);
    const int bh = blockIdx.y;
    const int qt = (gridDim.x - 1) - blockIdx.x;   // longest first
    const int q0 = qt * 128;
    const int NT = 2 * (qt + 1);

    const __half* Qb = Q + (size_t)bh * SEQ * HS;
    const __half* Kb = K + (size_t)bh * SEQ * HS;
    const __half* Vb = V + (size_t)bh * SEQ * HS;

    {
        const int row = tid >> 1, cb4 = (tid & 1) * 4;
        #pragma unroll
        for (int i = 0; i < 4; i++)
            *(uint4*)&Qs[row][(cb4 + i) * 8] =
                *(const uint4*)(Qb + (size_t)(q0 + row) * HS + (cb4 + i) * 8);
    }
    const int krow = tid >> 2, kb2 = (tid & 3) * 2;
    {
        #pragma unroll
        for (int i = 0; i < 2; i++) {
            cp16(smem_u32(&Ks[0][krow][(kb2 + i) * 8]), Kb + (size_t)krow * HS + (kb2 + i) * 8);
            cp16(smem_u32(&Vs[0][krow][(kb2 + i) * 8]), Vb + (size_t)krow * HS + (kb2 + i) * 8);
        }
        CP_COMMIT();
    }
    __syncthreads();

    uint32_t qa[4][4];
    {
        const int a_r = 16 * wid + (lane & 15), a_c = 8 * (lane >> 4);
        #pragma unroll
        for (int t = 0; t < 4; ++t)
            ldsm4(qa[t], smem_u32(&Qs[a_r][16 * t + a_c]));
    }

    float o[8][4];
    #pragma unroll
    for (int j = 0; j < 8; ++j)
        #pragma unroll
        for (int f = 0; f < 4; ++f) o[j][f] = 0.f;
    float rsacc[4] = {0.f, 0.f, 0.f, 0.f};
    const int gq0 = q0 + 16 * wid + lr;
    const int gq1 = gq0 + 8;
    const bool lowhalf = (wid < 4);

    const int nb_r = (lane & 7) + 8 * (lane >> 4), nb_c = 8 * ((lane >> 3) & 1);
    const int tb_r = (lane & 7) + 8 * ((lane >> 3) & 1), tb_c = 8 * (lane >> 4);

    for (int kt = 0; kt < NT; ++kt) {
        if (kt + 1 < NT) {
            const int nb = (kt + 1) & 1;
            const int k0n = (kt + 1) * 64;
            #pragma unroll
            for (int i = 0; i < 2; i++) {
                cp16(smem_u32(&Ks[nb][krow][(kb2 + i) * 8]),
                     Kb + (size_t)(k0n + krow) * HS + (kb2 + i) * 8);
                cp16(smem_u32(&Vs[nb][krow][(kb2 + i) * 8]),
                     Vb + (size_t)(k0n + krow) * HS + (kb2 + i) * 8);
            }
            CP_COMMIT();
            CP_WAIT1();
        } else {
            CP_WAIT0();
        }
        __syncthreads();

        const bool skiptile = lowhalf && (kt == NT - 1);
        if (!skiptile) {
            const int cb = kt & 1;
            const int k0 = kt * 64;
            const bool domask = (kt == NT - (lowhalf ? 2 : 1));

            uint32_t pa[4][4];
            #pragma unroll
            for (int jp = 0; jp < 4; ++jp) {
                float s0[4] = {0.f, 0.f, 0.f, 0.f};
                float s1[4] = {0.f, 0.f, 0.f, 0.f};
                #pragma unroll
                for (int t = 0; t < 4; ++t) {
                    uint32_t kb[4];
                    ldsm4(kb, smem_u32(&Ks[cb][16 * jp + nb_r][16 * t + nb_c]));
                    hmma(s0, qa[t], kb[0], kb[1]);
                    hmma(s1, qa[t], kb[2], kb[3]);
                }
                float v00 = s0[0], v01 = s0[1], v02 = s0[2], v03 = s0[3];
                float v10 = s1[0], v11 = s1[1], v12 = s1[2], v13 = s1[3];
                if (domask) {
                    const int keyb = k0 + 16 * jp + lc2;
                    v00 = (keyb     <= gq0) ? v00 : -1e4f;
                    v01 = (keyb + 1 <= gq0) ? v01 : -1e4f;
                    v02 = (keyb     <= gq1) ? v02 : -1e4f;
                    v03 = (keyb + 1 <= gq1) ? v03 : -1e4f;
                    v10 = (keyb + 8 <= gq0) ? v10 : -1e4f;
                    v11 = (keyb + 9 <= gq0) ? v11 : -1e4f;
                    v12 = (keyb + 8 <= gq1) ? v12 : -1e4f;
                    v13 = (keyb + 9 <= gq1) ? v13 : -1e4f;
                }
                pa[jp][0] = h2exp2(pack2(v00, v01));
                pa[jp][1] = h2exp2(pack2(v02, v03));
                pa[jp][2] = h2exp2(pack2(v10, v11));
                pa[jp][3] = h2exp2(pack2(v12, v13));
                hmma(rsacc, pa[jp], ONES2, ONES2);
            }
            #pragma unroll
            for (int dp = 0; dp < 4; ++dp) {
                #pragma unroll
                for (int t = 0; t < 4; ++t) {
                    uint32_t vbf[4];
                    ldsm4t(vbf, smem_u32(&Vs[cb][16 * t + tb_r][16 * dp + tb_c]));
                    hmma(o[2 * dp],     pa[t], vbf[0], vbf[1]);
                    hmma(o[2 * dp + 1], pa[t], vbf[2], vbf[3]);
                }
            }
        }
        __syncthreads();
    }

    const float inv0 = 1.f / rsacc[0], inv1 = 1.f / rsacc[2];
    const int b = bh >> 4, h = bh & 15;
    __half* d0 = O + ((size_t)(b * SEQ + gq0)) * EMB + h * HS;
    __half* d1 = O + ((size_t)(b * SEQ + gq1)) * EMB + h * HS;
    #pragma unroll
    for (int j = 0; j < 8; ++j) {
        const int d = 8 * j + lc2;
        *(__half2*)(d0 + d) = __floats2half2_rn(o[j][0] * inv0, o[j][1] * inv0);
        *(__half2*)(d1 + d) = __floats2half2_rn(o[j][2] * inv1, o[j][3] * inv1);
    }
}

// ---------------- launch ----------------
extern "C" void kernel_launch(void* const* d_in, const int* in_sizes, int n_in,
                              void* d_out, int out_size)
{
    const float* x  = (const float*)d_in[0];
    const float* Wq = (const float*)d_in[1];
    const float* Wk = (const float*)d_in[2];
    const float* Wv = (const float*)d_in[3];
    const float* Wp = (const float*)d_in[4];
    const float* bp = (const float*)d_in[5];
    float* out = (float*)d_out;

    __half *xh, *wq, *wk, *wv, *wp, *qh, *kh, *vh, *ah;
    cudaGetSymbolAddress((void**)&xh, g_xh);
    cudaGetSymbolAddress((void**)&wq, g_Wqh);
    cudaGetSymbolAddress((void**)&wk, g_Wkh);
    cudaGetSymbolAddress((void**)&wv, g_Wvh);
    cudaGetSymbolAddress((void**)&wp, g_Wph);
    cudaGetSymbolAddress((void**)&qh, g_Qh);
    cudaGetSymbolAddress((void**)&kh, g_Kh);
    cudaGetSymbolAddress((void**)&vh, g_Vh);
    cudaGetSymbolAddress((void**)&ah, g_Ah);

    cudaFuncSetAttribute(gemm_hmma<1>, cudaFuncAttributeMaxDynamicSharedMemorySize, GSMEM);
    cudaFuncSetAttribute(gemm_hmma<0>, cudaFuncAttributeMaxDynamicSharedMemorySize, GSMEM);
    cudaFuncSetAttribute(attn_hmma, cudaFuncAttributeMaxDynamicSharedMemorySize, ATTN_SMEM);

    cvt_x_kernel<<<MROWS * EMB / 1024, 256>>>(x, xh);
    cvt_w_kernel<<<dim3(EMB * EMB / 1024, 4), 256>>>(Wq, Wk, Wv, Wp, wq, wk, wv, wp);

    gemm_hmma<1><<<dim3(EMB / 128, MROWS / 128, 3), 256, GSMEM>>>(
        xh, wq, wk, wv, qh, kh, vh, nullptr, nullptr);

    attn_hmma<<<dim3(SEQ / 128, BATCH * NHEAD), 256, ATTN_SMEM>>>(qh, kh, vh, ah);

    gemm_hmma<0><<<dim3(EMB / 128, MROWS / 128, 1), 256, GSMEM>>>(
        ah, wp, nullptr, nullptr, nullptr, nullptr, nullptr, out, bp);
}

// round 16
// speedup vs baseline: 1.1225x; 1.0158x over previous
#include <cuda_runtime.h>
#include <cuda_fp16.h>
#include <cstdint>

#define BATCH 2
#define SEQ   2048
#define EMB   1024
#define NHEAD 16
#define HS    64
#define MROWS 4096
// exp(s/32) = 2^(s * CEXP), folded into Q at projection time
#define CEXP  0.045084294f

// ---------------- scratch (device globals) ----------------
__device__ __half g_xh[MROWS * EMB];
__device__ __half g_Wqh[EMB * EMB];   // fp16, K-major [k][n]
__device__ __half g_Wkh[EMB * EMB];
__device__ __half g_Wvh[EMB * EMB];
__device__ __half g_Wph[EMB * EMB];
__device__ __half g_Qh[MROWS * EMB];  // [b,h,t,d], pre-scaled by CEXP
__device__ __half g_Kh[MROWS * EMB];  // [b,h,t,d]
__device__ __half g_Vh[MROWS * EMB];  // [b,h,t,d]
__device__ __half g_Ah[MROWS * EMB];  // [b*t, h*64+d]

// ---------------- helpers ----------------
__device__ __forceinline__ uint32_t smem_u32(const void* p) {
    uint32_t a;
    asm("{ .reg .u64 t; cvta.to.shared.u64 t, %1; cvt.u32.u64 %0, t; }" : "=r"(a) : "l"(p));
    return a;
}
__device__ __forceinline__ void cp16(uint32_t saddr, const void* g) {
    asm volatile("cp.async.cg.shared.global [%0], [%1], 16;" :: "r"(saddr), "l"(g));
}
#define CP_COMMIT() asm volatile("cp.async.commit_group;" ::: "memory")
#define CP_WAIT0()  asm volatile("cp.async.wait_group 0;" ::: "memory")
#define CP_WAIT1()  asm volatile("cp.async.wait_group 1;" ::: "memory")

__device__ __forceinline__ void hmma(float* c, const uint32_t* a, uint32_t b0, uint32_t b1) {
    asm volatile("mma.sync.aligned.m16n8k16.row.col.f32.f16.f16.f32 "
        "{%0,%1,%2,%3}, {%4,%5,%6,%7}, {%8,%9}, {%0,%1,%2,%3};"
        : "+f"(c[0]), "+f"(c[1]), "+f"(c[2]), "+f"(c[3])
        : "r"(a[0]), "r"(a[1]), "r"(a[2]), "r"(a[3]), "r"(b0), "r"(b1));
}
__device__ __forceinline__ void ldsm4(uint32_t* r, uint32_t addr) {
    asm volatile("ldmatrix.sync.aligned.m8n8.x4.shared.b16 {%0,%1,%2,%3}, [%4];"
        : "=r"(r[0]), "=r"(r[1]), "=r"(r[2]), "=r"(r[3]) : "r"(addr));
}
__device__ __forceinline__ void ldsm4t(uint32_t* r, uint32_t addr) {
    asm volatile("ldmatrix.sync.aligned.m8n8.x4.trans.shared.b16 {%0,%1,%2,%3}, [%4];"
        : "=r"(r[0]), "=r"(r[1]), "=r"(r[2]), "=r"(r[3]) : "r"(addr));
}
__device__ __forceinline__ uint32_t pack2(float a, float b) {
    __half2 h = __floats2half2_rn(a, b);
    return *(uint32_t*)&h;
}
__device__ __forceinline__ uint32_t h2exp2(uint32_t x) {
    uint32_t r;
    asm("ex2.approx.f16x2 %0, %1;" : "=r"(r) : "r"(x));
    return r;
}
#define ONES2 0x3C003C00u   // half2(1, 1)

// ---------------- conversion kernels (round-5 proven) ----------------
__global__ __launch_bounds__(256) void cvt_x_kernel(const float* __restrict__ x,
                                                    __half* __restrict__ xh) {
    int i = (blockIdx.x * 256 + threadIdx.x) * 4;
    float4 v = *(const float4*)(x + i);
    *(__half2*)(xh + i)     = __floats2half2_rn(v.x, v.y);
    *(__half2*)(xh + i + 2) = __floats2half2_rn(v.z, v.w);
}

__global__ __launch_bounds__(256) void cvt_w_kernel(
    const float* __restrict__ W0, const float* __restrict__ W1,
    const float* __restrict__ W2, const float* __restrict__ W3,
    __half* __restrict__ D0, __half* __restrict__ D1,
    __half* __restrict__ D2, __half* __restrict__ D3)
{
    const int z = blockIdx.y;
    const float* W = (z == 0) ? W0 : (z == 1) ? W1 : (z == 2) ? W2 : W3;
    __half* D = (z == 0) ? D0 : (z == 1) ? D1 : (z == 2) ? D2 : D3;
    int i = (blockIdx.x * 256 + threadIdx.x) * 4;
    float4 v = *(const float4*)(W + i);
    *(__half2*)(D + i)     = __floats2half2_rn(v.x, v.y);
    *(__half2*)(D + i + 2) = __floats2half2_rn(v.z, v.w);
}

// ---------------- HMMA GEMM (round-12 proven: 3-stage, 1 barrier) ----------
#define ASTR 40    // A smem stride (32 + 8 pad halves)
#define BSTR 136   // B smem stride (128 + 8 pad halves)
#define ABUF (128 * ASTR)              // 5120 halves per A stage
#define BBUF (32 * BSTR)               // 4352 halves per B stage
#define GSMEM (3 * (ABUF + BBUF) * 2)  // 56832 B

template <int FUSED>
__global__ __launch_bounds__(256, 2)
void gemm_hmma(const __half* __restrict__ A,
               const __half* __restrict__ B0, const __half* __restrict__ B1,
               const __half* __restrict__ B2,
               __half* __restrict__ D0, __half* __restrict__ D1,
               __half* __restrict__ D2,
               float* __restrict__ Dout, const float* __restrict__ bias)
{
    extern __shared__ __align__(16) __half gsm[];

    const int tid = threadIdx.x, wid = tid >> 5, lane = tid & 31;
    const int bn = blockIdx.x * 128, bm = blockIdx.y * 128;
    const int z = FUSED ? blockIdx.z : 0;
    const __half* B = FUSED ? ((z == 0) ? B0 : (z == 1) ? B1 : B2) : B0;
    const int mw = (wid & 1) * 64, nw = (wid >> 1) * 32;
    const int lr = lane >> 2, lc2 = 2 * (lane & 3);

    float acc[4][4][4];
    #pragma unroll
    for (int i = 0; i < 4; i++)
        #pragma unroll
        for (int j = 0; j < 4; j++)
            #pragma unroll
            for (int f = 0; f < 4; f++) acc[i][j][f] = 0.f;

    const int arow = tid >> 1, acb = (tid & 1) * 2;
    const int br0 = tid >> 4, bc0 = tid & 15;
    const int br1 = (tid + 256) >> 4, bc1 = bc0;

    auto stage = [&](int s, int k0) {
        __half (*as)[ASTR] = (__half(*)[ASTR])(gsm + (size_t)s * ABUF);
        __half (*bs)[BSTR] = (__half(*)[BSTR])(gsm + 3 * ABUF + (size_t)s * BBUF);
        const __half* Ag = A + (size_t)(bm + arow) * EMB + k0;
        #pragma unroll
        for (int i = 0; i < 2; i++)
            cp16(smem_u32(&as[arow][(acb + i) * 8]), Ag + (acb + i) * 8);
        cp16(smem_u32(&bs[br0][bc0 * 8]), B + (size_t)(k0 + br0) * EMB + bn + bc0 * 8);
        cp16(smem_u32(&bs[br1][bc1 * 8]), B + (size_t)(k0 + br1) * EMB + bn + bc1 * 8);
        CP_COMMIT();
    };

    stage(0, 0);
    stage(1, 32);

    const int a_r = lane & 15, a_c = 8 * (lane >> 4);
    const int b_r = (lane & 7) + 8 * ((lane >> 3) & 1), b_c = 8 * (lane >> 4);

    for (int kt = 0; kt < 32; ++kt) {
        if (kt + 1 < 32) CP_WAIT1(); else CP_WAIT0();
        __syncthreads();                       // all warps done with kt-1 compute
        if (kt + 2 < 32) stage((kt + 2) % 3, (kt + 2) * 32);

        const int cb = kt % 3;
        __half (*As)[ASTR] = (__half(*)[ASTR])(gsm + (size_t)cb * ABUF);
        __half (*Bs)[BSTR] = (__half(*)[BSTR])(gsm + 3 * ABUF + (size_t)cb * BBUF);
        #pragma unroll
        for (int kk = 0; kk < 2; ++kk) {
            uint32_t a[4][4], b[4][2];
            #pragma unroll
            for (int am = 0; am < 4; ++am)
                ldsm4(a[am], smem_u32(&As[mw + 16 * am + a_r][16 * kk + a_c]));
            #pragma unroll
            for (int anp = 0; anp < 2; ++anp) {
                uint32_t bt[4];
                ldsm4t(bt, smem_u32(&Bs[16 * kk + b_r][nw + 16 * anp + b_c]));
                b[2 * anp][0] = bt[0]; b[2 * anp][1] = bt[1];
                b[2 * anp + 1][0] = bt[2]; b[2 * anp + 1][1] = bt[3];
            }
            #pragma unroll
            for (int am = 0; am < 4; ++am)
                #pragma unroll
                for (int an = 0; an < 4; ++an)
                    hmma(acc[am][an], a[am], b[an][0], b[an][1]);
        }
    }

    __half* Dh = FUSED ? ((z == 0) ? D0 : (z == 1) ? D1 : D2) : D0;
    const float qs = (FUSED && z == 0) ? CEXP : 1.f;   // fold softmax scale into Q
    #pragma unroll
    for (int am = 0; am < 4; ++am) {
        #pragma unroll
        for (int an = 0; an < 4; ++an) {
            const int r0 = bm + mw + 16 * am + lr;
            const int r1 = r0 + 8;
            const int c0 = bn + nw + 8 * an + lc2;
            float v0 = acc[am][an][0], v1 = acc[am][an][1];
            float v2 = acc[am][an][2], v3 = acc[am][an][3];
            if (FUSED) {   // head-split fp16 [b,h,t,d]
                v0 *= qs; v1 *= qs; v2 *= qs; v3 *= qs;
                const int h = c0 >> 6, d = c0 & 63;
                const int b0i = r0 >> 11, t0 = r0 & 2047;
                const int b1i = r1 >> 11, t1 = r1 & 2047;
                *(__half2*)&Dh[((size_t)((b0i * NHEAD + h) * SEQ + t0)) * HS + d] =
                    __floats2half2_rn(v0, v1);
                *(__half2*)&Dh[((size_t)((b1i * NHEAD + h) * SEQ + t1)) * HS + d] =
                    __floats2half2_rn(v2, v3);
            } else {       // fp32 + bias
                const float bb0 = bias[c0], bb1 = bias[c0 + 1];
                float2 o0 = make_float2(v0 + bb0, v1 + bb1);
                float2 o1 = make_float2(v2 + bb0, v3 + bb1);
                *(float2*)&Dout[(size_t)r0 * EMB + c0] = o0;
                *(float2*)&Dout[(size_t)r1 * EMB + c0] = o1;
            }
        }
    }
}

// ---------------- HMMA flash attention ----------------
// Round-9 compute structure + round-12 pipeline protocol:
// 3-stage K/V ring, ONE __syncthreads per 64-key tile.
#define KSTR 72
#define QBUF (128 * KSTR)              // 9216 halves
#define KVBUF (64 * KSTR)              // 4608 halves per stage per array
#define ATTN_SMEM ((QBUF + 6 * KVBUF) * 2)   // 73728 B

__global__ __launch_bounds__(256)
void attn_hmma(const __half* __restrict__ Q, const __half* __restrict__ K,
               const __half* __restrict__ V, __half* __restrict__ O)
{
    extern __shared__ __align__(16) __half dsm[];
    __half (*Qs)[KSTR] = (__half(*)[KSTR])dsm;
    // Ks stage s: dsm + QBUF + s*KVBUF ; Vs stage s: dsm + QBUF + 3*KVBUF + s*KVBUF

    const int tid = threadIdx.x, wid = tid >> 5, lane = tid & 31;
    const int lr = lane >> 2, lc2 = 2 * (lane & 3);
    const int bh = blockIdx.y;
    const int qt = (gridDim.x - 1) - blockIdx.x;   // longest first
    const int q0 = qt * 128;
    const int NT = 2 * (qt + 1);

    const __half* Qb = Q + (size_t)bh * SEQ * HS;
    const __half* Kb = K + (size_t)bh * SEQ * HS;
    const __half* Vb = V + (size_t)bh * SEQ * HS;

    const int krow = tid >> 2, kb2 = (tid & 3) * 2;
    auto stage = [&](int s, int k0) {
        __half (*ks)[KSTR] = (__half(*)[KSTR])(dsm + QBUF + (size_t)s * KVBUF);
        __half (*vs)[KSTR] = (__half(*)[KSTR])(dsm + QBUF + 3 * KVBUF + (size_t)s * KVBUF);
        #pragma unroll
        for (int i = 0; i < 2; i++) {
            cp16(smem_u32(&ks[krow][(kb2 + i) * 8]), Kb + (size_t)(k0 + krow) * HS + (kb2 + i) * 8);
            cp16(smem_u32(&vs[krow][(kb2 + i) * 8]), Vb + (size_t)(k0 + krow) * HS + (kb2 + i) * 8);
        }
        CP_COMMIT();
    };

    // stage Q (plain stores) + prefetch K/V stages 0,1
    {
        const int row = tid >> 1, cb4 = (tid & 1) * 4;
        #pragma unroll
        for (int i = 0; i < 4; i++)
            *(uint4*)&Qs[row][(cb4 + i) * 8] =
                *(const uint4*)(Qb + (size_t)(q0 + row) * HS + (cb4 + i) * 8);
    }
    stage(0, 0);
    if (NT > 1) stage(1, 64);
    __syncthreads();   // Q visible (also covers stage-0 ordering via wait below)

    uint32_t qa[4][4];
    {
        const int a_r = 16 * wid + (lane & 15), a_c = 8 * (lane >> 4);
        #pragma unroll
        for (int t = 0; t < 4; ++t)
            ldsm4(qa[t], smem_u32(&Qs[a_r][16 * t + a_c]));
    }

    float o[8][4];
    #pragma unroll
    for (int j = 0; j < 8; ++j)
        #pragma unroll
        for (int f = 0; f < 4; ++f) o[j][f] = 0.f;
    float rsacc[4] = {0.f, 0.f, 0.f, 0.f};
    const int gq0 = q0 + 16 * wid + lr;
    const int gq1 = gq0 + 8;
    const bool lowhalf = (wid < 4);

    const int nb_r = (lane & 7) + 8 * (lane >> 4), nb_c = 8 * ((lane >> 3) & 1);
    const int tb_r = (lane & 7) + 8 * ((lane >> 3) & 1), tb_c = 8 * (lane >> 4);

    for (int kt = 0; kt < NT; ++kt) {
        if (kt + 1 < NT) CP_WAIT1(); else CP_WAIT0();
        __syncthreads();                       // all warps done with kt-1 compute
        if (kt + 2 < NT) stage((kt + 2) % 3, (kt + 2) * 64);

        const bool skiptile = lowhalf && (kt == NT - 1);
        if (!skiptile) {
            const int cb = kt % 3;
            __half (*Ks)[KSTR] = (__half(*)[KSTR])(dsm + QBUF + (size_t)cb * KVBUF);
            __half (*Vs)[KSTR] = (__half(*)[KSTR])(dsm + QBUF + 3 * KVBUF + (size_t)cb * KVBUF);
            const int k0 = kt * 64;
            const bool domask = (kt == NT - (lowhalf ? 2 : 1));

            uint32_t pa[4][4];
            #pragma unroll
            for (int jp = 0; jp < 4; ++jp) {
                float s0[4] = {0.f, 0.f, 0.f, 0.f};
                float s1[4] = {0.f, 0.f, 0.f, 0.f};
                #pragma unroll
                for (int t = 0; t < 4; ++t) {
                    uint32_t kb[4];
                    ldsm4(kb, smem_u32(&Ks[16 * jp + nb_r][16 * t + nb_c]));
                    hmma(s0, qa[t], kb[0], kb[1]);
                    hmma(s1, qa[t], kb[2], kb[3]);
                }
                float v00 = s0[0], v01 = s0[1], v02 = s0[2], v03 = s0[3];
                float v10 = s1[0], v11 = s1[1], v12 = s1[2], v13 = s1[3];
                if (domask) {
                    const int keyb = k0 + 16 * jp + lc2;
                    v00 = (keyb     <= gq0) ? v00 : -1e4f;
                    v01 = (keyb + 1 <= gq0) ? v01 : -1e4f;
                    v02 = (keyb     <= gq1) ? v02 : -1e4f;
                    v03 = (keyb + 1 <= gq1) ? v03 : -1e4f;
                    v10 = (keyb + 8 <= gq0) ? v10 : -1e4f;
                    v11 = (keyb + 9 <= gq0) ? v11 : -1e4f;
                    v12 = (keyb + 8 <= gq1) ? v12 : -1e4f;
                    v13 = (keyb + 9 <= gq1) ? v13 : -1e4f;
                }
                pa[jp][0] = h2exp2(pack2(v00, v01));
                pa[jp][1] = h2exp2(pack2(v02, v03));
                pa[jp][2] = h2exp2(pack2(v10, v11));
                pa[jp][3] = h2exp2(pack2(v12, v13));
                hmma(rsacc, pa[jp], ONES2, ONES2);
            }
            #pragma unroll
            for (int dp = 0; dp < 4; ++dp) {
                #pragma unroll
                for (int t = 0; t < 4; ++t) {
                    uint32_t vbf[4];
                    ldsm4t(vbf, smem_u32(&Vs[16 * t + tb_r][16 * dp + tb_c]));
                    hmma(o[2 * dp],     pa[t], vbf[0], vbf[1]);
                    hmma(o[2 * dp + 1], pa[t], vbf[2], vbf[3]);
                }
            }
        }
    }

    const float inv0 = 1.f / rsacc[0], inv1 = 1.f / rsacc[2];
    const int b = bh >> 4, h = bh & 15;
    __half* d0 = O + ((size_t)(b * SEQ + gq0)) * EMB + h * HS;
    __half* d1 = O + ((size_t)(b * SEQ + gq1)) * EMB + h * HS;
    #pragma unroll
    for (int j = 0; j < 8; ++j) {
        const int d = 8 * j + lc2;
        *(__half2*)(d0 + d) = __floats2half2_rn(o[j][0] * inv0, o[j][1] * inv0);
        *(__half2*)(d1 + d) = __floats2half2_rn(o[j][2] * inv1, o[j][3] * inv1);
    }
}

// ---------------- launch ----------------
extern "C" void kernel_launch(void* const* d_in, const int* in_sizes, int n_in,
                              void* d_out, int out_size)
{
    const float* x  = (const float*)d_in[0];
    const float* Wq = (const float*)d_in[1];
    const float* Wk = (const float*)d_in[2];
    const float* Wv = (const float*)d_in[3];
    const float* Wp = (const float*)d_in[4];
    const float* bp = (const float*)d_in[5];
    float* out = (float*)d_out;

    __half *xh, *wq, *wk, *wv, *wp, *qh, *kh, *vh, *ah;
    cudaGetSymbolAddress((void**)&xh, g_xh);
    cudaGetSymbolAddress((void**)&wq, g_Wqh);
    cudaGetSymbolAddress((void**)&wk, g_Wkh);
    cudaGetSymbolAddress((void**)&wv, g_Wvh);
    cudaGetSymbolAddress((void**)&wp, g_Wph);
    cudaGetSymbolAddress((void**)&qh, g_Qh);
    cudaGetSymbolAddress((void**)&kh, g_Kh);
    cudaGetSymbolAddress((void**)&vh, g_Vh);
    cudaGetSymbolAddress((void**)&ah, g_Ah);

    cudaFuncSetAttribute(gemm_hmma<1>, cudaFuncAttributeMaxDynamicSharedMemorySize, GSMEM);
    cudaFuncSetAttribute(gemm_hmma<0>, cudaFuncAttributeMaxDynamicSharedMemorySize, GSMEM);
    cudaFuncSetAttribute(attn_hmma, cudaFuncAttributeMaxDynamicSharedMemorySize, ATTN_SMEM);

    cvt_x_kernel<<<MROWS * EMB / 1024, 256>>>(x, xh);
    cvt_w_kernel<<<dim3(EMB * EMB / 1024, 4), 256>>>(Wq, Wk, Wv, Wp, wq, wk, wv, wp);

    gemm_hmma<1><<<dim3(EMB / 128, MROWS / 128, 3), 256, GSMEM>>>(
        xh, wq, wk, wv, qh, kh, vh, nullptr, nullptr);

    attn_hmma<<<dim3(SEQ / 128, BATCH * NHEAD), 256, ATTN_SMEM>>>(qh, kh, vh, ah);

    gemm_hmma<0><<<dim3(EMB / 128, MROWS / 128, 1), 256, GSMEM>>>(
        ah, wp, nullptr, nullptr, nullptr, nullptr, nullptr, out, bp);
}